// round 12
// baseline (speedup 1.0000x reference)
#include <cuda_runtime.h>

#define HW   36864      // 192*192
#define SIMG 37249      // 193*193
#define NB   6

// -------- scratch (static device globals: allocation-guard safe) --------
__device__ float g_x [NB*64*HW];     // x = [ctx ; extra], (b,c,y,px)
__device__ float g_S1[NB*64*SIMG];   // integral image of x
__device__ float g_S2[NB*64*SIMG];   // integral image of x*x
__device__ float g_wT[3*128*64];     // transposed scale weights [scale][k][o]

// -------- packed fp32x2 helpers (Blackwell fma.rn.f32x2) --------
__device__ __forceinline__ unsigned long long pk2(float lo, float hi) {
    unsigned long long r;
    asm("mov.b64 %0, {%1, %2};" : "=l"(r) : "f"(lo), "f"(hi));
    return r;
}
__device__ __forceinline__ void fma2(unsigned long long &d,
                                     unsigned long long a,
                                     unsigned long long b) {
    asm("fma.rn.f32x2 %0, %1, %2, %0;" : "+l"(d) : "l"(a), "l"(b));
}

// ============================================================================
// K0: transpose scale weights into g_wT[scale][k*64+o] = ws[o*128+k].
// ============================================================================
__global__ void k0_kernel(const float* __restrict__ ws0,
                          const float* __restrict__ ws1,
                          const float* __restrict__ ws2)
{
    const float* ws = (blockIdx.x == 0) ? ws0 : (blockIdx.x == 1) ? ws1 : ws2;
    float* dst = g_wT + blockIdx.x * 8192;
    for (int idx = threadIdx.x; idx < 8192; idx += blockDim.x) {
        int o = idx >> 7, k = idx & 127;
        dst[k*64 + o] = ws[idx];
    }
}

// ============================================================================
// K1: x = [W_ctx@feature+b_ctx ; extra] -> g_x,
// out0 = W1@x+b1 -> output channels [0,68). One CTA per (y,b) row, 288 thr.
// ============================================================================
__global__ __launch_bounds__(288, 2) void k1_kernel(
    const float* __restrict__ feature, const float* __restrict__ extra,
    const float* __restrict__ w_ctx,   const float* __restrict__ b_ctx,
    const float* __restrict__ w1,      const float* __restrict__ b1,
    float* __restrict__ out)
{
    extern __shared__ float sm[];
    float* s_wc = sm;            // 1024   : wcT[k*32+o]
    float* s_w1 = sm + 1024;     // 4608   : w1T[k*72+o], o padded 68->72
    float* s_f  = sm + 5632;     // 6144   : feature row [32][192]
    float* s_x  = sm + 11776;    // 12288  : x row [64][192]
    const int tid = threadIdx.x;
    const int y = blockIdx.x, b = blockIdx.y;
    const int fb = b / 3;        // jnp.repeat(...,3,axis=0): [b0,b0,b0,b1,b1,b1]

    for (int idx = tid; idx < 1024; idx += 288) {
        int o = idx >> 5, k = idx & 31;
        s_wc[k*32 + o] = w_ctx[idx];
    }
    for (int idx = tid; idx < 72*64; idx += 288) {
        int o = idx >> 6, k = idx & 63;
        s_w1[k*72 + o] = (o < 68) ? w1[o*64 + k] : 0.f;
    }
    const float* fbase = feature + (fb*32)*HW + y*192;
    const float* ebase = extra   + (b*32)*HW + y*192;
    for (int idx = tid; idx < 32*192; idx += 288) {
        int c = idx / 192, px = idx - c*192;
        s_f[idx]              = fbase[c*HW + px];
        s_x[(32+c)*192 + px]  = ebase[c*HW + px];
    }
    __syncthreads();

    // ctx GEMM: 32 out x 192 px, K=32 (256 threads: 2 out x 12 px each)
    if (tid < 256) {
        const int og = tid >> 4, pg = tid & 15;
        const int o0 = og*2, pxb = pg*12;
        unsigned long long acc[2][6];
        {
            unsigned long long p0 = pk2(b_ctx[o0],   b_ctx[o0]);
            unsigned long long p1 = pk2(b_ctx[o0+1], b_ctx[o0+1]);
            #pragma unroll
            for (int j = 0; j < 6; j++) { acc[0][j] = p0; acc[1][j] = p1; }
        }
        #pragma unroll 4
        for (int k = 0; k < 32; k++) {
            float wa = s_wc[k*32 + o0], wb = s_wc[k*32 + o0 + 1];
            unsigned long long wpa = pk2(wa, wa), wpb = pk2(wb, wb);
            #pragma unroll
            for (int j = 0; j < 6; j++) {
                unsigned long long m =
                    *(const unsigned long long*)(s_f + k*192 + pxb + 2*j);
                fma2(acc[0][j], wpa, m);
                fma2(acc[1][j], wpb, m);
            }
        }
        #pragma unroll
        for (int j = 0; j < 6; j++) {
            *(unsigned long long*)(s_x + o0*192     + pxb + 2*j) = acc[0][j];
            *(unsigned long long*)(s_x + (o0+1)*192 + pxb + 2*j) = acc[1][j];
        }
    }
    __syncthreads();

    // write x row to global
    {
        float* gx = g_x + (b*64)*HW + y*192;
        for (int idx = tid; idx < 64*96; idx += 288) {
            int c = idx / 96, pp = (idx - c*96)*2;
            *(unsigned long long*)(gx + c*HW + pp) =
                *(const unsigned long long*)(s_x + c*192 + pp);
        }
    }

    // out0 GEMM: 72(pad) out x 192 px, K=64 (288 threads: 4 out x 12 px each)
    {
        const int og = tid >> 4, pg = tid & 15;   // og 0..17
        const int o0 = og*4, pxb = pg*12;
        unsigned long long acc[4][6];
        #pragma unroll
        for (int i = 0; i < 4; i++) {
            int o = o0 + i;
            float bb = (o < 68) ? b1[o] : 0.f;
            unsigned long long p = pk2(bb, bb);
            #pragma unroll
            for (int j = 0; j < 6; j++) acc[i][j] = p;
        }
        #pragma unroll 2
        for (int k = 0; k < 64; k++) {
            float4 w4 = *(const float4*)(s_w1 + k*72 + o0);
            unsigned long long w0 = pk2(w4.x, w4.x), wA = pk2(w4.y, w4.y);
            unsigned long long w2 = pk2(w4.z, w4.z), w3 = pk2(w4.w, w4.w);
            #pragma unroll
            for (int j = 0; j < 6; j++) {
                unsigned long long m =
                    *(const unsigned long long*)(s_x + k*192 + pxb + 2*j);
                fma2(acc[0][j], w0, m);
                fma2(acc[1][j], wA, m);
                fma2(acc[2][j], w2, m);
                fma2(acc[3][j], w3, m);
            }
        }
        #pragma unroll
        for (int i = 0; i < 4; i++) {
            int o = o0 + i;
            if (o < 68) {
                float* op = out + (b*260 + o)*HW + y*192 + pxb;
                #pragma unroll
                for (int j = 0; j < 6; j++)
                    *(unsigned long long*)(op + 2*j) = acc[i][j];
            }
        }
    }
}

// ============================================================================
// K2: per-row prefix sums of x and x*x into S1,S2 rows [y+1], with left pad.
// ============================================================================
__global__ void k2_kernel()
{
    const int warp = threadIdx.x >> 5, lane = threadIdx.x & 31;
    const int row  = blockIdx.x * 8 + warp;        // < 6*64*192 = 73728
    const int img  = row / 192, y = row - img*192;
    const float* xr = g_x + row*192;

    float s1p[6], s2p[6];
    float a1 = 0.f, a2 = 0.f;
    #pragma unroll
    for (int j = 0; j < 6; j++) {
        float v = xr[lane*6 + j];
        a1 += v;      s1p[j] = a1;
        a2 += v * v;  s2p[j] = a2;
    }
    float t1 = a1, t2 = a2;
    #pragma unroll
    for (int off = 1; off < 32; off <<= 1) {
        float n1 = __shfl_up_sync(0xffffffffu, t1, off);
        float n2 = __shfl_up_sync(0xffffffffu, t2, off);
        if (lane >= off) { t1 += n1; t2 += n2; }
    }
    float e1 = __shfl_up_sync(0xffffffffu, t1, 1);
    float e2 = __shfl_up_sync(0xffffffffu, t2, 1);
    if (lane == 0) { e1 = 0.f; e2 = 0.f; }

    float* S1r = g_S1 + img*SIMG + (y+1)*193;
    float* S2r = g_S2 + img*SIMG + (y+1)*193;
    if (lane == 0) { S1r[0] = 0.f; S2r[0] = 0.f; }
    #pragma unroll
    for (int j = 0; j < 6; j++) {
        S1r[1 + lane*6 + j] = e1 + s1p[j];
        S2r[1 + lane*6 + j] = e2 + s2p[j];
    }
    if (y == 0) {  // zero pad row 0
        float* Z1 = g_S1 + img*SIMG;
        float* Z2 = g_S2 + img*SIMG;
        for (int j = lane; j < 193; j += 32) { Z1[j] = 0.f; Z2[j] = 0.f; }
    }
}

// ============================================================================
// K3: in-place column accumulation -> full 2D integral images.
// ============================================================================
__global__ void k3_kernel()
{
    const int img = blockIdx.x;
    float* S = ((blockIdx.y == 0) ? g_S1 : g_S2) + img*SIMG;
    const int t = threadIdx.x;
    if (t >= 193) return;
    float s = 0.f;
    float v[8];
    #pragma unroll
    for (int j = 0; j < 8; j++) v[j] = S[(1 + j)*193 + t];
    for (int r0 = 1; r0 <= 192; r0 += 8) {
        float w[8];
        if (r0 + 8 <= 192) {
            #pragma unroll
            for (int j = 0; j < 8; j++) w[j] = S[(r0 + 8 + j)*193 + t];
        }
        #pragma unroll
        for (int j = 0; j < 8; j++) { s += v[j]; S[(r0 + j)*193 + t] = s; }
        #pragma unroll
        for (int j = 0; j < 8; j++) v[j] = w[j];
    }
}

// ============================================================================
// K4 v8 = v4 skeleton, weights moved smem -> L1-resident global (g_wT):
//   per (scale, b, y): full 192-px row, 192 threads (6 warps), 58KB smem,
//   3 CTAs/SM (18 warps). Phase B weight reads are warp-uniform LDG.128
//   (single 16B L1 request, cheaper than a 4-wavefront LDS broadcast);
//   m reads stay XOR-swizzled LDS.128. Per warp-k: 8 smem wf + 2 uniform
//   LDG per 32 fma2 -> fma-pipe binding with LSU slack.
//   2 K-chunks as in v4 (big sync quantum); no register prefetch (reg cap
//   113 at occ 3: acc 64 + temps ~40 fits).
// ============================================================================
__global__ __launch_bounds__(192, 3) void k4_kernel(
    const float* __restrict__ bs0, const float* __restrict__ bs1,
    const float* __restrict__ bs2, float* __restrict__ out)
{
    extern __shared__ float sm[];
    float* s_m = sm;            // 12288 : [64 k][192 px] chunk of mean/var
    float* s_d = sm + 12288;    // 2496  : per-warp D1/D2 (208 each)
    const int tid = threadIdx.x, warp = tid >> 5, lane = tid & 31;
    const int so = lane >> 3, sp = lane & 7;     // out-sub, px-sub
    const int ogx = warp / 3, pg = warp % 3;     // out-half, px-third
    const int y = blockIdx.x;
    const int z = blockIdx.y;
    const int scale = z / 6, b = z - scale*6;
    const int half = (scale == 0) ? 2 : (scale == 1) ? 4 : 8;
    const float* bs = (scale == 0) ? bs0 : (scale == 1) ? bs1 : bs2;
    const float* wT = g_wT + scale * 8192;

    const int y0 = max(y - half, 0);
    const int y1 = min(y + 1 + half, 192);
    const float hh = (float)(y1 - y0);
    const int offA = y0*193, offB = y1*193;

    // phase-A per-lane inverse areas (px = lane + 32*q)
    float inva6[6];
    #pragma unroll
    for (int q = 0; q < 6; q++) {
        int px = lane + 32*q;
        int x0 = max(px - half, 0), x1 = min(px + 1 + half, 192);
        inva6[q] = 1.0f / (hh * (float)(x1 - x0));
    }

    float* D1 = s_d + warp * 416;
    float* D2 = D1 + 208;

    // accumulators: 8 outs x 4 px-pairs, bias-initialized
    const int obase = ogx*32 + so*8;
    unsigned long long acc[8][4];
    #pragma unroll
    for (int i = 0; i < 8; i++) {
        float bb = bs[obase + i];
        unsigned long long p = pk2(bb, bb);
        acc[i][0] = p; acc[i][1] = p; acc[i][2] = p; acc[i][3] = p;
    }

    // XOR swizzle offsets (floats): lane loads 16B halves in swapped order
    const int offS = (sp & 4) ? 4 : 0;   // first load float offset
    const int offT = 4 - offS;           // second load float offset

    #pragma unroll
    for (int chunk = 0; chunk < 2; chunk++) {
        const int chb = chunk * 32;
        // ---------------- Phase A: channels chb..chb+31, stride-6 per warp ----
        for (int c = warp; c < 32; c += 6) {
            const float* p1 = g_S1 + (b*64 + chb + c)*SIMG;
            const float* p2 = g_S2 + (b*64 + chb + c)*SIMG;
            #pragma unroll
            for (int jj = 0; jj < 7; jj++) {
                int j = lane + 32*jj;
                if (j < 193) {
                    D1[j] = p1[offB + j] - p1[offA + j];
                    D2[j] = p2[offB + j] - p2[offA + j];
                }
            }
            __syncwarp();
            #pragma unroll
            for (int q = 0; q < 6; q++) {
                int px = lane + 32*q;
                int i0 = max(px - half, 0);
                int i1 = min(px + 1 + half, 192);
                float s1 = D1[i1] - D1[i0];
                float s2 = D2[i1] - D2[i0];
                float m = s1 * inva6[q];
                float v = s2 * inva6[q] - m*m;
                s_m[c*192 + px]        = m;
                s_m[(32 + c)*192 + px] = v;
            }
            __syncwarp();
        }
        __syncthreads();

        // ---------------- Phase B: 64-k GEMM slice ----------------
        #pragma unroll
        for (int hsel = 0; hsel < 2; hsel++) {
            // weight k rows: hsel=0 -> mean ks (chb..), hsel=1 -> var ks (64+chb..)
            const float* wp = wT + (hsel*64 + chb)*64 + obase;
            const float* mp = s_m + (hsel*32)*192 + pg*64 + sp*8;
            #pragma unroll 2
            for (int kk = 0; kk < 32; kk++) {
                float4 wa = *(const float4*)(wp);        // uniform LDG.128, L1
                float4 wb = *(const float4*)(wp + 4);
                ulonglong2 mA = *(const ulonglong2*)(mp + offS);
                ulonglong2 mB = *(const ulonglong2*)(mp + offT);
                unsigned long long w0 = pk2(wa.x, wa.x), w1 = pk2(wa.y, wa.y);
                unsigned long long w2 = pk2(wa.z, wa.z), w3 = pk2(wa.w, wa.w);
                unsigned long long w4 = pk2(wb.x, wb.x), w5 = pk2(wb.y, wb.y);
                unsigned long long w6 = pk2(wb.z, wb.z), w7 = pk2(wb.w, wb.w);
                fma2(acc[0][0], w0, mA.x); fma2(acc[0][1], w0, mA.y);
                fma2(acc[0][2], w0, mB.x); fma2(acc[0][3], w0, mB.y);
                fma2(acc[1][0], w1, mA.x); fma2(acc[1][1], w1, mA.y);
                fma2(acc[1][2], w1, mB.x); fma2(acc[1][3], w1, mB.y);
                fma2(acc[2][0], w2, mA.x); fma2(acc[2][1], w2, mA.y);
                fma2(acc[2][2], w2, mB.x); fma2(acc[2][3], w2, mB.y);
                fma2(acc[3][0], w3, mA.x); fma2(acc[3][1], w3, mA.y);
                fma2(acc[3][2], w3, mB.x); fma2(acc[3][3], w3, mB.y);
                fma2(acc[4][0], w4, mA.x); fma2(acc[4][1], w4, mA.y);
                fma2(acc[4][2], w4, mB.x); fma2(acc[4][3], w4, mB.y);
                fma2(acc[5][0], w5, mA.x); fma2(acc[5][1], w5, mA.y);
                fma2(acc[5][2], w5, mB.x); fma2(acc[5][3], w5, mB.y);
                fma2(acc[6][0], w6, mA.x); fma2(acc[6][1], w6, mA.y);
                fma2(acc[6][2], w6, mB.x); fma2(acc[6][3], w6, mB.y);
                fma2(acc[7][0], w7, mA.x); fma2(acc[7][1], w7, mA.y);
                fma2(acc[7][2], w7, mB.x); fma2(acc[7][3], w7, mB.y);
                wp += 64; mp += 192;
            }
        }
        if (chunk == 0) __syncthreads();   // protect s_m before next phase A
    }

    // store: acc[i][0..1] -> pixels at sp*8+offS(+2); acc[i][2..3] -> sp*8+offT(+2)
    const int pA = sp*8 + offS, pB = sp*8 + offT;
    float* ob = out + (b*260 + 68 + scale*64 + obase)*HW + y*192 + pg*64;
    #pragma unroll
    for (int i = 0; i < 8; i++) {
        float* op = ob + i*HW;
        *(unsigned long long*)(op + pA)     = acc[i][0];
        *(unsigned long long*)(op + pA + 2) = acc[i][1];
        *(unsigned long long*)(op + pB)     = acc[i][2];
        *(unsigned long long*)(op + pB + 2) = acc[i][3];
    }
}

// ============================================================================
extern "C" void kernel_launch(void* const* d_in, const int* in_sizes, int n_in,
                              void* d_out, int out_size)
{
    const float* feature = (const float*)d_in[0];
    const float* extra   = (const float*)d_in[1];
    const float* w_ctx   = (const float*)d_in[2];
    const float* b_ctx   = (const float*)d_in[3];
    const float* w1      = (const float*)d_in[4];
    const float* b1      = (const float*)d_in[5];
    const float* ws0     = (const float*)d_in[6];
    const float* bs0     = (const float*)d_in[7];
    const float* ws1     = (const float*)d_in[8];
    const float* bs1     = (const float*)d_in[9];
    const float* ws2     = (const float*)d_in[10];
    const float* bs2     = (const float*)d_in[11];
    float* out = (float*)d_out;

    cudaFuncSetAttribute(k1_kernel, cudaFuncAttributeMaxDynamicSharedMemorySize, 96256);
    cudaFuncSetAttribute(k4_kernel, cudaFuncAttributeMaxDynamicSharedMemorySize, 59392);

    k0_kernel<<<3, 256>>>(ws0, ws1, ws2);
    k1_kernel<<<dim3(192, 6), 288, 96256>>>(feature, extra, w_ctx, b_ctx, w1, b1, out);
    k2_kernel<<<9216, 256>>>();
    k3_kernel<<<dim3(384, 2), 224>>>();
    k4_kernel<<<dim3(192, 18), 192, 59392>>>(bs0, bs1, bs2, out);
}

// round 14
// speedup vs baseline: 1.1261x; 1.1261x over previous
#include <cuda_runtime.h>

#define HW   36864      // 192*192
#define SIMG 37249      // 193*193
#define NB   6

// -------- scratch (static device globals: allocation-guard safe) --------
__device__ float g_x [NB*64*HW];     // x = [ctx ; extra], (b,c,y,px)
__device__ float g_S1[NB*64*SIMG];   // integral image of x
__device__ float g_S2[NB*64*SIMG];   // integral image of x*x

// -------- packed fp32x2 helpers (Blackwell fma.rn.f32x2) --------
__device__ __forceinline__ unsigned long long pk2(float lo, float hi) {
    unsigned long long r;
    asm("mov.b64 %0, {%1, %2};" : "=l"(r) : "f"(lo), "f"(hi));
    return r;
}
__device__ __forceinline__ void fma2(unsigned long long &d,
                                     unsigned long long a,
                                     unsigned long long b) {
    asm("fma.rn.f32x2 %0, %1, %2, %0;" : "+l"(d) : "l"(a), "l"(b));
}

// ============================================================================
// K1: x = [W_ctx@feature+b_ctx ; extra] -> g_x,
// out0 = W1@x+b1 -> output channels [0,68). One CTA per (y,b) row, 288 thr.
// ============================================================================
__global__ __launch_bounds__(288, 2) void k1_kernel(
    const float* __restrict__ feature, const float* __restrict__ extra,
    const float* __restrict__ w_ctx,   const float* __restrict__ b_ctx,
    const float* __restrict__ w1,      const float* __restrict__ b1,
    float* __restrict__ out)
{
    extern __shared__ float sm[];
    float* s_wc = sm;            // 1024   : wcT[k*32+o]
    float* s_w1 = sm + 1024;     // 4608   : w1T[k*72+o], o padded 68->72
    float* s_f  = sm + 5632;     // 6144   : feature row [32][192]
    float* s_x  = sm + 11776;    // 12288  : x row [64][192]
    const int tid = threadIdx.x;
    const int y = blockIdx.x, b = blockIdx.y;
    const int fb = b / 3;        // jnp.repeat(...,3,axis=0): [b0,b0,b0,b1,b1,b1]

    for (int idx = tid; idx < 1024; idx += 288) {
        int o = idx >> 5, k = idx & 31;
        s_wc[k*32 + o] = w_ctx[idx];
    }
    for (int idx = tid; idx < 72*64; idx += 288) {
        int o = idx >> 6, k = idx & 63;
        s_w1[k*72 + o] = (o < 68) ? w1[o*64 + k] : 0.f;
    }
    const float* fbase = feature + (fb*32)*HW + y*192;
    const float* ebase = extra   + (b*32)*HW + y*192;
    for (int idx = tid; idx < 32*192; idx += 288) {
        int c = idx / 192, px = idx - c*192;
        s_f[idx]              = fbase[c*HW + px];
        s_x[(32+c)*192 + px]  = ebase[c*HW + px];
    }
    __syncthreads();

    // ctx GEMM: 32 out x 192 px, K=32 (256 threads: 2 out x 12 px each)
    if (tid < 256) {
        const int og = tid >> 4, pg = tid & 15;
        const int o0 = og*2, pxb = pg*12;
        unsigned long long acc[2][6];
        {
            unsigned long long p0 = pk2(b_ctx[o0],   b_ctx[o0]);
            unsigned long long p1 = pk2(b_ctx[o0+1], b_ctx[o0+1]);
            #pragma unroll
            for (int j = 0; j < 6; j++) { acc[0][j] = p0; acc[1][j] = p1; }
        }
        #pragma unroll 4
        for (int k = 0; k < 32; k++) {
            float wa = s_wc[k*32 + o0], wb = s_wc[k*32 + o0 + 1];
            unsigned long long wpa = pk2(wa, wa), wpb = pk2(wb, wb);
            #pragma unroll
            for (int j = 0; j < 6; j++) {
                unsigned long long m =
                    *(const unsigned long long*)(s_f + k*192 + pxb + 2*j);
                fma2(acc[0][j], wpa, m);
                fma2(acc[1][j], wpb, m);
            }
        }
        #pragma unroll
        for (int j = 0; j < 6; j++) {
            *(unsigned long long*)(s_x + o0*192     + pxb + 2*j) = acc[0][j];
            *(unsigned long long*)(s_x + (o0+1)*192 + pxb + 2*j) = acc[1][j];
        }
    }
    __syncthreads();

    // write x row to global
    {
        float* gx = g_x + (b*64)*HW + y*192;
        for (int idx = tid; idx < 64*96; idx += 288) {
            int c = idx / 96, pp = (idx - c*96)*2;
            *(unsigned long long*)(gx + c*HW + pp) =
                *(const unsigned long long*)(s_x + c*192 + pp);
        }
    }

    // out0 GEMM: 72(pad) out x 192 px, K=64 (288 threads: 4 out x 12 px each)
    {
        const int og = tid >> 4, pg = tid & 15;   // og 0..17
        const int o0 = og*4, pxb = pg*12;
        unsigned long long acc[4][6];
        #pragma unroll
        for (int i = 0; i < 4; i++) {
            int o = o0 + i;
            float bb = (o < 68) ? b1[o] : 0.f;
            unsigned long long p = pk2(bb, bb);
            #pragma unroll
            for (int j = 0; j < 6; j++) acc[i][j] = p;
        }
        #pragma unroll 2
        for (int k = 0; k < 64; k++) {
            float4 w4 = *(const float4*)(s_w1 + k*72 + o0);
            unsigned long long w0 = pk2(w4.x, w4.x), wA = pk2(w4.y, w4.y);
            unsigned long long w2 = pk2(w4.z, w4.z), w3 = pk2(w4.w, w4.w);
            #pragma unroll
            for (int j = 0; j < 6; j++) {
                unsigned long long m =
                    *(const unsigned long long*)(s_x + k*192 + pxb + 2*j);
                fma2(acc[0][j], w0, m);
                fma2(acc[1][j], wA, m);
                fma2(acc[2][j], w2, m);
                fma2(acc[3][j], w3, m);
            }
        }
        #pragma unroll
        for (int i = 0; i < 4; i++) {
            int o = o0 + i;
            if (o < 68) {
                float* op = out + (b*260 + o)*HW + y*192 + pxb;
                #pragma unroll
                for (int j = 0; j < 6; j++)
                    *(unsigned long long*)(op + 2*j) = acc[i][j];
            }
        }
    }
}

// ============================================================================
// K2: per-row prefix sums of x and x*x into S1,S2 rows [y+1], with left pad.
// ============================================================================
__global__ void k2_kernel()
{
    const int warp = threadIdx.x >> 5, lane = threadIdx.x & 31;
    const int row  = blockIdx.x * 8 + warp;        // < 6*64*192 = 73728
    const int img  = row / 192, y = row - img*192;
    const float* xr = g_x + row*192;

    float s1p[6], s2p[6];
    float a1 = 0.f, a2 = 0.f;
    #pragma unroll
    for (int j = 0; j < 6; j++) {
        float v = xr[lane*6 + j];
        a1 += v;      s1p[j] = a1;
        a2 += v * v;  s2p[j] = a2;
    }
    float t1 = a1, t2 = a2;
    #pragma unroll
    for (int off = 1; off < 32; off <<= 1) {
        float n1 = __shfl_up_sync(0xffffffffu, t1, off);
        float n2 = __shfl_up_sync(0xffffffffu, t2, off);
        if (lane >= off) { t1 += n1; t2 += n2; }
    }
    float e1 = __shfl_up_sync(0xffffffffu, t1, 1);
    float e2 = __shfl_up_sync(0xffffffffu, t2, 1);
    if (lane == 0) { e1 = 0.f; e2 = 0.f; }

    float* S1r = g_S1 + img*SIMG + (y+1)*193;
    float* S2r = g_S2 + img*SIMG + (y+1)*193;
    if (lane == 0) { S1r[0] = 0.f; S2r[0] = 0.f; }
    #pragma unroll
    for (int j = 0; j < 6; j++) {
        S1r[1 + lane*6 + j] = e1 + s1p[j];
        S2r[1 + lane*6 + j] = e2 + s2p[j];
    }
    if (y == 0) {  // zero pad row 0
        float* Z1 = g_S1 + img*SIMG;
        float* Z2 = g_S2 + img*SIMG;
        for (int j = lane; j < 193; j += 32) { Z1[j] = 0.f; Z2[j] = 0.f; }
    }
}

// ============================================================================
// K3: in-place column accumulation -> full 2D integral images.
// ============================================================================
__global__ void k3_kernel()
{
    const int img = blockIdx.x;
    float* S = ((blockIdx.y == 0) ? g_S1 : g_S2) + img*SIMG;
    const int t = threadIdx.x;
    if (t >= 193) return;
    float s = 0.f;
    float v[8];
    #pragma unroll
    for (int j = 0; j < 8; j++) v[j] = S[(1 + j)*193 + t];
    for (int r0 = 1; r0 <= 192; r0 += 8) {
        float w[8];
        if (r0 + 8 <= 192) {
            #pragma unroll
            for (int j = 0; j < 8; j++) w[j] = S[(r0 + 8 + j)*193 + t];
        }
        #pragma unroll
        for (int j = 0; j < 8; j++) { s += v[j]; S[(r0 + j)*193 + t] = s; }
        #pragma unroll
        for (int j = 0; j < 8; j++) v[j] = w[j];
    }
}

// ============================================================================
// K4 v9 = v4 inner loop at half-row CTAs for 3 CTAs/SM:
//   per (scale, b, y, 96-px half): 192 threads (6 warps), 62KB smem,
//   3 CTAs/SM = 18 warps. Lane tile 8o x 4px (acc 16 u64 = 32 regs);
//   warp = 32o x 32px; CTA = 64o x 96px. Per warp-k: w 2xLDS.128
//   (octet-phase broadcast) + m 1xLDS.128 (16B lane stride: conflict-free,
//   NO swizzle needed) -> 12 wf per 16 fma2 + 16 alu-movs.
//   Same 2-chunk quantum as v4; phase A covers 96px (+halo <= 113 cols).
// ============================================================================
__global__ __launch_bounds__(192, 3) void k4_kernel(
    const float* __restrict__ ws0, const float* __restrict__ bs0,
    const float* __restrict__ ws1, const float* __restrict__ bs1,
    const float* __restrict__ ws2, const float* __restrict__ bs2,
    float* __restrict__ out)
{
    extern __shared__ float sm[];
    float* s_w = sm;            // 8192 floats : wT[k*64+o]
    float* s_m = sm + 8192;     // 6144 floats : [64 k][96 px] chunk of mean/var
    float* s_d = sm + 14336;    // 1536 floats : per-warp D1/D2 (128 each)
    const int tid = threadIdx.x, warp = tid >> 5, lane = tid & 31;
    const int so = lane >> 3, sp = lane & 7;     // out-sub, px-sub
    const int ogx = warp / 3, pg = warp % 3;     // out-half, px-third(32px)
    const int px0 = blockIdx.x * 96;             // row half
    const int y = blockIdx.y;
    const int z = blockIdx.z;
    const int scale = z / 6, b = z - scale*6;
    const int half = (scale == 0) ? 2 : (scale == 1) ? 4 : 8;
    const float* ws = (scale == 0) ? ws0 : (scale == 1) ? ws1 : ws2;
    const float* bs = (scale == 0) ? bs0 : (scale == 1) ? bs1 : bs2;

    // load + transpose weights: s_w[k*64+o] = ws[o*128+k]
    for (int idx = tid; idx < 8192; idx += 192) {
        int o = idx >> 7, k = idx & 127;
        s_w[k*64 + o] = ws[idx];
    }

    const int y0 = max(y - half, 0);
    const int y1 = min(y + 1 + half, 192);
    const float hh = (float)(y1 - y0);
    const int c0 = max(px0 - half, 0);
    const int c1 = min(px0 + 96 + half, 192);
    const int nseg = c1 - c0 + 1;                // <= 113
    const int offA = y0*193 + c0, offB = y1*193 + c0;

    // phase-A per-lane inverse areas (px = lane + 32*q, q<3)
    float inva3[3];
    #pragma unroll
    for (int q = 0; q < 3; q++) {
        int gpx = px0 + lane + 32*q;
        int x0 = max(gpx - half, 0), x1 = min(gpx + 1 + half, 192);
        inva3[q] = 1.0f / (hh * (float)(x1 - x0));
    }

    float* D1 = s_d + warp * 256;
    float* D2 = D1 + 128;

    // accumulators: 8 outs x 2 px-pairs (4 px), bias-initialized
    const int obase = ogx*32 + so*8;
    unsigned long long acc[8][2];
    #pragma unroll
    for (int i = 0; i < 8; i++) {
        float bb = bs[obase + i];
        unsigned long long p = pk2(bb, bb);
        acc[i][0] = p; acc[i][1] = p;
    }

    #pragma unroll
    for (int chunk = 0; chunk < 2; chunk++) {
        const int chb = chunk * 32;
        // ------- Phase A: channels chb..chb+31, stride-6 per warp -------
        for (int c = warp; c < 32; c += 6) {
            const float* p1 = g_S1 + (b*64 + chb + c)*SIMG;
            const float* p2 = g_S2 + (b*64 + chb + c)*SIMG;
            #pragma unroll
            for (int jj = 0; jj < 4; jj++) {
                int j = lane + 32*jj;
                if (j < nseg) {
                    D1[j] = p1[offB + j] - p1[offA + j];
                    D2[j] = p2[offB + j] - p2[offA + j];
                }
            }
            __syncwarp();
            #pragma unroll
            for (int q = 0; q < 3; q++) {
                int px = lane + 32*q;
                int gpx = px0 + px;
                int i0 = max(gpx - half, 0) - c0;
                int i1 = min(gpx + 1 + half, 192) - c0;
                float s1 = D1[i1] - D1[i0];
                float s2 = D2[i1] - D2[i0];
                float m = s1 * inva3[q];
                float v = s2 * inva3[q] - m*m;
                s_m[c*96 + px]        = m;
                s_m[(32 + c)*96 + px] = v;
            }
            __syncwarp();
        }
        __syncthreads();

        // ------- Phase B: 64-k GEMM slice -------
        #pragma unroll
        for (int hsel = 0; hsel < 2; hsel++) {
            const float* wp = s_w + (hsel*64 + chb)*64 + obase;
            const float* mp = s_m + (hsel*32)*96 + pg*32 + sp*4;
            #pragma unroll 4
            for (int kk = 0; kk < 32; kk++) {
                float4 wa = *(const float4*)(wp);
                float4 wb = *(const float4*)(wp + 4);
                ulonglong2 mA = *(const ulonglong2*)(mp);
                unsigned long long w0 = pk2(wa.x, wa.x), w1 = pk2(wa.y, wa.y);
                unsigned long long w2 = pk2(wa.z, wa.z), w3 = pk2(wa.w, wa.w);
                unsigned long long w4 = pk2(wb.x, wb.x), w5 = pk2(wb.y, wb.y);
                unsigned long long w6 = pk2(wb.z, wb.z), w7 = pk2(wb.w, wb.w);
                fma2(acc[0][0], w0, mA.x); fma2(acc[0][1], w0, mA.y);
                fma2(acc[1][0], w1, mA.x); fma2(acc[1][1], w1, mA.y);
                fma2(acc[2][0], w2, mA.x); fma2(acc[2][1], w2, mA.y);
                fma2(acc[3][0], w3, mA.x); fma2(acc[3][1], w3, mA.y);
                fma2(acc[4][0], w4, mA.x); fma2(acc[4][1], w4, mA.y);
                fma2(acc[5][0], w5, mA.x); fma2(acc[5][1], w5, mA.y);
                fma2(acc[6][0], w6, mA.x); fma2(acc[6][1], w6, mA.y);
                fma2(acc[7][0], w7, mA.x); fma2(acc[7][1], w7, mA.y);
                wp += 64; mp += 96;
            }
        }
        if (chunk == 0) __syncthreads();   // protect s_m before next phase A
    }

    // store: 4 contiguous px per out -> one 16B store
    float* ob = out + (b*260 + 68 + scale*64 + obase)*HW + y*192
                    + px0 + pg*32 + sp*4;
    #pragma unroll
    for (int i = 0; i < 8; i++) {
        ulonglong2 v;
        v.x = acc[i][0]; v.y = acc[i][1];
        *(ulonglong2*)(ob + i*HW) = v;
    }
}

// ============================================================================
extern "C" void kernel_launch(void* const* d_in, const int* in_sizes, int n_in,
                              void* d_out, int out_size)
{
    const float* feature = (const float*)d_in[0];
    const float* extra   = (const float*)d_in[1];
    const float* w_ctx   = (const float*)d_in[2];
    const float* b_ctx   = (const float*)d_in[3];
    const float* w1      = (const float*)d_in[4];
    const float* b1      = (const float*)d_in[5];
    const float* ws0     = (const float*)d_in[6];
    const float* bs0     = (const float*)d_in[7];
    const float* ws1     = (const float*)d_in[8];
    const float* bs1     = (const float*)d_in[9];
    const float* ws2     = (const float*)d_in[10];
    const float* bs2     = (const float*)d_in[11];
    float* out = (float*)d_out;

    cudaFuncSetAttribute(k1_kernel, cudaFuncAttributeMaxDynamicSharedMemorySize, 96256);
    cudaFuncSetAttribute(k4_kernel, cudaFuncAttributeMaxDynamicSharedMemorySize, 63488);

    k1_kernel<<<dim3(192, 6), 288, 96256>>>(feature, extra, w_ctx, b_ctx, w1, b1, out);
    k2_kernel<<<9216, 256>>>();
    k3_kernel<<<dim3(384, 2), 224>>>();
    k4_kernel<<<dim3(2, 192, 18), 192, 63488>>>(ws0, bs0, ws1, bs1, ws2, bs2, out);
}

// round 15
// speedup vs baseline: 1.3356x; 1.1860x over previous
#include <cuda_runtime.h>

#define HW   36864      // 192*192
#define SIMG 37249      // 193*193
#define NB   6

// -------- scratch (static device globals: allocation-guard safe) --------
__device__ float g_x [NB*64*HW];     // x = [ctx ; extra], (b,c,y,px)
__device__ float g_S1[NB*64*SIMG];   // integral image of x
__device__ float g_S2[NB*64*SIMG];   // integral image of x*x

// -------- packed fp32x2 helpers (Blackwell fma.rn.f32x2) --------
__device__ __forceinline__ unsigned long long pk2(float lo, float hi) {
    unsigned long long r;
    asm("mov.b64 %0, {%1, %2};" : "=l"(r) : "f"(lo), "f"(hi));
    return r;
}
__device__ __forceinline__ void fma2(unsigned long long &d,
                                     unsigned long long a,
                                     unsigned long long b) {
    asm("fma.rn.f32x2 %0, %1, %2, %0;" : "+l"(d) : "l"(a), "l"(b));
}

// ============================================================================
// K1: x = [W_ctx@feature+b_ctx ; extra] -> g_x,
// out0 = W1@x+b1 -> output channels [0,68). One CTA per (y,b) row, 288 thr.
// ============================================================================
__global__ __launch_bounds__(288, 2) void k1_kernel(
    const float* __restrict__ feature, const float* __restrict__ extra,
    const float* __restrict__ w_ctx,   const float* __restrict__ b_ctx,
    const float* __restrict__ w1,      const float* __restrict__ b1,
    float* __restrict__ out)
{
    extern __shared__ float sm[];
    float* s_wc = sm;            // 1024   : wcT[k*32+o]
    float* s_w1 = sm + 1024;     // 4608   : w1T[k*72+o], o padded 68->72
    float* s_f  = sm + 5632;     // 6144   : feature row [32][192]
    float* s_x  = sm + 11776;    // 12288  : x row [64][192]
    const int tid = threadIdx.x;
    const int y = blockIdx.x, b = blockIdx.y;
    const int fb = b / 3;        // jnp.repeat(...,3,axis=0): [b0,b0,b0,b1,b1,b1]

    for (int idx = tid; idx < 1024; idx += 288) {
        int o = idx >> 5, k = idx & 31;
        s_wc[k*32 + o] = w_ctx[idx];
    }
    for (int idx = tid; idx < 72*64; idx += 288) {
        int o = idx >> 6, k = idx & 63;
        s_w1[k*72 + o] = (o < 68) ? w1[o*64 + k] : 0.f;
    }
    const float* fbase = feature + (fb*32)*HW + y*192;
    const float* ebase = extra   + (b*32)*HW + y*192;
    for (int idx = tid; idx < 32*192; idx += 288) {
        int c = idx / 192, px = idx - c*192;
        s_f[idx]              = fbase[c*HW + px];
        s_x[(32+c)*192 + px]  = ebase[c*HW + px];
    }
    __syncthreads();

    // ctx GEMM: 32 out x 192 px, K=32 (256 threads: 2 out x 12 px each)
    if (tid < 256) {
        const int og = tid >> 4, pg = tid & 15;
        const int o0 = og*2, pxb = pg*12;
        unsigned long long acc[2][6];
        {
            unsigned long long p0 = pk2(b_ctx[o0],   b_ctx[o0]);
            unsigned long long p1 = pk2(b_ctx[o0+1], b_ctx[o0+1]);
            #pragma unroll
            for (int j = 0; j < 6; j++) { acc[0][j] = p0; acc[1][j] = p1; }
        }
        #pragma unroll 4
        for (int k = 0; k < 32; k++) {
            float wa = s_wc[k*32 + o0], wb = s_wc[k*32 + o0 + 1];
            unsigned long long wpa = pk2(wa, wa), wpb = pk2(wb, wb);
            #pragma unroll
            for (int j = 0; j < 6; j++) {
                unsigned long long m =
                    *(const unsigned long long*)(s_f + k*192 + pxb + 2*j);
                fma2(acc[0][j], wpa, m);
                fma2(acc[1][j], wpb, m);
            }
        }
        #pragma unroll
        for (int j = 0; j < 6; j++) {
            *(unsigned long long*)(s_x + o0*192     + pxb + 2*j) = acc[0][j];
            *(unsigned long long*)(s_x + (o0+1)*192 + pxb + 2*j) = acc[1][j];
        }
    }
    __syncthreads();

    // write x row to global
    {
        float* gx = g_x + (b*64)*HW + y*192;
        for (int idx = tid; idx < 64*96; idx += 288) {
            int c = idx / 96, pp = (idx - c*96)*2;
            *(unsigned long long*)(gx + c*HW + pp) =
                *(const unsigned long long*)(s_x + c*192 + pp);
        }
    }

    // out0 GEMM: 72(pad) out x 192 px, K=64 (288 threads: 4 out x 12 px each)
    {
        const int og = tid >> 4, pg = tid & 15;   // og 0..17
        const int o0 = og*4, pxb = pg*12;
        unsigned long long acc[4][6];
        #pragma unroll
        for (int i = 0; i < 4; i++) {
            int o = o0 + i;
            float bb = (o < 68) ? b1[o] : 0.f;
            unsigned long long p = pk2(bb, bb);
            #pragma unroll
            for (int j = 0; j < 6; j++) acc[i][j] = p;
        }
        #pragma unroll 2
        for (int k = 0; k < 64; k++) {
            float4 w4 = *(const float4*)(s_w1 + k*72 + o0);
            unsigned long long w0 = pk2(w4.x, w4.x), wA = pk2(w4.y, w4.y);
            unsigned long long w2 = pk2(w4.z, w4.z), w3 = pk2(w4.w, w4.w);
            #pragma unroll
            for (int j = 0; j < 6; j++) {
                unsigned long long m =
                    *(const unsigned long long*)(s_x + k*192 + pxb + 2*j);
                fma2(acc[0][j], w0, m);
                fma2(acc[1][j], wA, m);
                fma2(acc[2][j], w2, m);
                fma2(acc[3][j], w3, m);
            }
        }
        #pragma unroll
        for (int i = 0; i < 4; i++) {
            int o = o0 + i;
            if (o < 68) {
                float* op = out + (b*260 + o)*HW + y*192 + pxb;
                #pragma unroll
                for (int j = 0; j < 6; j++)
                    *(unsigned long long*)(op + 2*j) = acc[i][j];
            }
        }
    }
}

// ============================================================================
// K2: per-row prefix sums of x and x*x into S1,S2 rows [y+1], with left pad.
// ============================================================================
__global__ void k2_kernel()
{
    const int warp = threadIdx.x >> 5, lane = threadIdx.x & 31;
    const int row  = blockIdx.x * 8 + warp;        // < 6*64*192 = 73728
    const int img  = row / 192, y = row - img*192;
    const float* xr = g_x + row*192;

    float s1p[6], s2p[6];
    float a1 = 0.f, a2 = 0.f;
    #pragma unroll
    for (int j = 0; j < 6; j++) {
        float v = xr[lane*6 + j];
        a1 += v;      s1p[j] = a1;
        a2 += v * v;  s2p[j] = a2;
    }
    float t1 = a1, t2 = a2;
    #pragma unroll
    for (int off = 1; off < 32; off <<= 1) {
        float n1 = __shfl_up_sync(0xffffffffu, t1, off);
        float n2 = __shfl_up_sync(0xffffffffu, t2, off);
        if (lane >= off) { t1 += n1; t2 += n2; }
    }
    float e1 = __shfl_up_sync(0xffffffffu, t1, 1);
    float e2 = __shfl_up_sync(0xffffffffu, t2, 1);
    if (lane == 0) { e1 = 0.f; e2 = 0.f; }

    float* S1r = g_S1 + img*SIMG + (y+1)*193;
    float* S2r = g_S2 + img*SIMG + (y+1)*193;
    if (lane == 0) { S1r[0] = 0.f; S2r[0] = 0.f; }
    #pragma unroll
    for (int j = 0; j < 6; j++) {
        S1r[1 + lane*6 + j] = e1 + s1p[j];
        S2r[1 + lane*6 + j] = e2 + s2p[j];
    }
    if (y == 0) {  // zero pad row 0
        float* Z1 = g_S1 + img*SIMG;
        float* Z2 = g_S2 + img*SIMG;
        for (int j = lane; j < 193; j += 32) { Z1[j] = 0.f; Z2[j] = 0.f; }
    }
}

// ============================================================================
// K3: in-place column accumulation -> full 2D integral images.
// ============================================================================
__global__ void k3_kernel()
{
    const int img = blockIdx.x;
    float* S = ((blockIdx.y == 0) ? g_S1 : g_S2) + img*SIMG;
    const int t = threadIdx.x;
    if (t >= 193) return;
    float s = 0.f;
    float v[8];
    #pragma unroll
    for (int j = 0; j < 8; j++) v[j] = S[(1 + j)*193 + t];
    for (int r0 = 1; r0 <= 192; r0 += 8) {
        float w[8];
        if (r0 + 8 <= 192) {
            #pragma unroll
            for (int j = 0; j < 8; j++) w[j] = S[(r0 + 8 + j)*193 + t];
        }
        #pragma unroll
        for (int j = 0; j < 8; j++) { s += v[j]; S[(r0 + j)*193 + t] = s; }
        #pragma unroll
        for (int j = 0; j < 8; j++) v[j] = w[j];
    }
}

// ============================================================================
// K4 v10: 8-warp CTA (256 thr) for BALANCED SMSP mapping (2/SMSP per CTA,
// 4/SMSP at 2 CTAs/SM) — fixes the 4/4/2/2 imbalance every 6-warp variant had.
//   CTA: full 192-px row, 64 outs, K in 2 chunks of 64 k. 93KB smem.
//   Warp: 32o x 48px (ogx = warp>>2, pg = warp&3).
//   Lane: 8o x 6px as 3 px-pairs at 16B stride:
//     m = 3x LDS.64 (8 distinct addrs, 4-way broadcast, conflict-free, 2 wf ea)
//     w = 2x uniform-per-octet LDS.128 (4 wf ea) + 16 movs.
//   Per warp-k: 14 wf : 24 fma2 -> fma 12 vs LSU 14 SM-cyc, near-balanced.
//   acc 24 u64 = 48 regs; total ~90 of 128 cap -> ptxas pipelining slack.
//   Phase A identical to v4 (4 channels per warp now).
// ============================================================================
__global__ __launch_bounds__(256, 2) void k4_kernel(
    const float* __restrict__ ws0, const float* __restrict__ bs0,
    const float* __restrict__ ws1, const float* __restrict__ bs1,
    const float* __restrict__ ws2, const float* __restrict__ bs2,
    float* __restrict__ out)
{
    extern __shared__ float sm[];
    float* s_w = sm;            // 8192  : wT[k*64+o]
    float* s_m = sm + 8192;     // 12288 : [64 k][192 px] chunk of mean/var
    float* s_d = sm + 20480;    // 3328  : per-warp D1/D2 (208 each)
    const int tid = threadIdx.x, warp = tid >> 5, lane = tid & 31;
    const int so = lane >> 3, sp = lane & 7;     // out-sub, px-sub
    const int ogx = warp >> 2, pg = warp & 3;    // out-half, px-quarter (48px)
    const int y = blockIdx.x;
    const int z = blockIdx.y;
    const int scale = z / 6, b = z - scale*6;
    const int half = (scale == 0) ? 2 : (scale == 1) ? 4 : 8;
    const float* ws = (scale == 0) ? ws0 : (scale == 1) ? ws1 : ws2;
    const float* bs = (scale == 0) ? bs0 : (scale == 1) ? bs1 : bs2;

    // load + transpose weights: s_w[k*64+o] = ws[o*128+k]
    for (int idx = tid; idx < 8192; idx += 256) {
        int o = idx >> 7, k = idx & 127;
        s_w[k*64 + o] = ws[idx];
    }

    const int y0 = max(y - half, 0);
    const int y1 = min(y + 1 + half, 192);
    const float hh = (float)(y1 - y0);
    const int offA = y0*193, offB = y1*193;

    // phase-A per-lane inverse areas (px = lane + 32*q)
    float inva6[6];
    #pragma unroll
    for (int q = 0; q < 6; q++) {
        int px = lane + 32*q;
        int x0 = max(px - half, 0), x1 = min(px + 1 + half, 192);
        inva6[q] = 1.0f / (hh * (float)(x1 - x0));
    }

    float* D1 = s_d + warp * 416;
    float* D2 = D1 + 208;

    // accumulators: 8 outs x 3 px-pairs, bias-initialized
    const int obase = ogx*32 + so*8;
    unsigned long long acc[8][3];
    #pragma unroll
    for (int i = 0; i < 8; i++) {
        float bb = bs[obase + i];
        unsigned long long p = pk2(bb, bb);
        acc[i][0] = p; acc[i][1] = p; acc[i][2] = p;
    }

    #pragma unroll
    for (int chunk = 0; chunk < 2; chunk++) {
        const int chb = chunk * 32;
        // ------- Phase A: channels chb..chb+31, 4 per warp -------
        #pragma unroll
        for (int i = 0; i < 4; i++) {
            const int c = warp + 8*i;              // local channel in [0,32)
            const float* p1 = g_S1 + (b*64 + chb + c)*SIMG;
            const float* p2 = g_S2 + (b*64 + chb + c)*SIMG;
            #pragma unroll
            for (int jj = 0; jj < 7; jj++) {
                int j = lane + 32*jj;
                if (j < 193) {
                    D1[j] = p1[offB + j] - p1[offA + j];
                    D2[j] = p2[offB + j] - p2[offA + j];
                }
            }
            __syncwarp();
            #pragma unroll
            for (int q = 0; q < 6; q++) {
                int px = lane + 32*q;
                int i0 = max(px - half, 0);
                int i1 = min(px + 1 + half, 192);
                float s1 = D1[i1] - D1[i0];
                float s2 = D2[i1] - D2[i0];
                float m = s1 * inva6[q];
                float v = s2 * inva6[q] - m*m;
                s_m[c*192 + px]        = m;
                s_m[(32 + c)*192 + px] = v;
            }
            __syncwarp();
        }
        __syncthreads();

        // ------- Phase B: 64-k GEMM slice -------
        #pragma unroll
        for (int hsel = 0; hsel < 2; hsel++) {
            // weight k rows: hsel=0 -> mean ks (chb..), hsel=1 -> var ks
            const float* wp = s_w + (hsel*64 + chb)*64 + obase;
            const float* mp = s_m + (hsel*32)*192 + pg*48 + sp*2;
            #pragma unroll 4
            for (int kk = 0; kk < 32; kk++) {
                float4 wa = *(const float4*)(wp);
                float4 wb = *(const float4*)(wp + 4);
                unsigned long long m0 = *(const unsigned long long*)(mp);
                unsigned long long m1 = *(const unsigned long long*)(mp + 16);
                unsigned long long m2 = *(const unsigned long long*)(mp + 32);
                unsigned long long w0 = pk2(wa.x, wa.x), w1 = pk2(wa.y, wa.y);
                unsigned long long w2 = pk2(wa.z, wa.z), w3 = pk2(wa.w, wa.w);
                unsigned long long w4 = pk2(wb.x, wb.x), w5 = pk2(wb.y, wb.y);
                unsigned long long w6 = pk2(wb.z, wb.z), w7 = pk2(wb.w, wb.w);
                fma2(acc[0][0], w0, m0); fma2(acc[0][1], w0, m1); fma2(acc[0][2], w0, m2);
                fma2(acc[1][0], w1, m0); fma2(acc[1][1], w1, m1); fma2(acc[1][2], w1, m2);
                fma2(acc[2][0], w2, m0); fma2(acc[2][1], w2, m1); fma2(acc[2][2], w2, m2);
                fma2(acc[3][0], w3, m0); fma2(acc[3][1], w3, m1); fma2(acc[3][2], w3, m2);
                fma2(acc[4][0], w4, m0); fma2(acc[4][1], w4, m1); fma2(acc[4][2], w4, m2);
                fma2(acc[5][0], w5, m0); fma2(acc[5][1], w5, m1); fma2(acc[5][2], w5, m2);
                fma2(acc[6][0], w6, m0); fma2(acc[6][1], w6, m1); fma2(acc[6][2], w6, m2);
                fma2(acc[7][0], w7, m0); fma2(acc[7][1], w7, m1); fma2(acc[7][2], w7, m2);
                wp += 64; mp += 192;
            }
        }
        if (chunk == 0) __syncthreads();   // protect s_m before next phase A
    }

    // store: 3 px-pairs per out at +0,+16,+32 floats
    float* ob = out + (b*260 + 68 + scale*64 + obase)*HW + y*192 + pg*48 + sp*2;
    #pragma unroll
    for (int i = 0; i < 8; i++) {
        float* op = ob + i*HW;
        *(unsigned long long*)(op)      = acc[i][0];
        *(unsigned long long*)(op + 16) = acc[i][1];
        *(unsigned long long*)(op + 32) = acc[i][2];
    }
}

// ============================================================================
extern "C" void kernel_launch(void* const* d_in, const int* in_sizes, int n_in,
                              void* d_out, int out_size)
{
    const float* feature = (const float*)d_in[0];
    const float* extra   = (const float*)d_in[1];
    const float* w_ctx   = (const float*)d_in[2];
    const float* b_ctx   = (const float*)d_in[3];
    const float* w1      = (const float*)d_in[4];
    const float* b1      = (const float*)d_in[5];
    const float* ws0     = (const float*)d_in[6];
    const float* bs0     = (const float*)d_in[7];
    const float* ws1     = (const float*)d_in[8];
    const float* bs1     = (const float*)d_in[9];
    const float* ws2     = (const float*)d_in[10];
    const float* bs2     = (const float*)d_in[11];
    float* out = (float*)d_out;

    cudaFuncSetAttribute(k1_kernel, cudaFuncAttributeMaxDynamicSharedMemorySize, 96256);
    cudaFuncSetAttribute(k4_kernel, cudaFuncAttributeMaxDynamicSharedMemorySize, 95744);

    k1_kernel<<<dim3(192, 6), 288, 96256>>>(feature, extra, w_ctx, b_ctx, w1, b1, out);
    k2_kernel<<<9216, 256>>>();
    k3_kernel<<<dim3(384, 2), 224>>>();
    k4_kernel<<<dim3(192, 18), 256, 95744>>>(ws0, bs0, ws1, bs1, ws2, bs2, out);
}

// round 16
// speedup vs baseline: 1.3470x; 1.0085x over previous
#include <cuda_runtime.h>

#define HW   36864      // 192*192
#define SIMG 37249      // 193*193
#define NB   6

// -------- scratch (static device globals: allocation-guard safe) --------
__device__ float g_x [NB*64*HW];     // x = [ctx ; extra], (b,c,y,px)
__device__ float g_S1[NB*64*SIMG];   // integral image of x
__device__ float g_S2[NB*64*SIMG];   // integral image of x*x

// -------- packed fp32x2 helpers (Blackwell fma.rn.f32x2) --------
__device__ __forceinline__ unsigned long long pk2(float lo, float hi) {
    unsigned long long r;
    asm("mov.b64 %0, {%1, %2};" : "=l"(r) : "f"(lo), "f"(hi));
    return r;
}
__device__ __forceinline__ void fma2(unsigned long long &d,
                                     unsigned long long a,
                                     unsigned long long b) {
    asm("fma.rn.f32x2 %0, %1, %2, %0;" : "+l"(d) : "l"(a), "l"(b));
}

// ============================================================================
// K1: x = [W_ctx@feature+b_ctx ; extra] -> g_x,
// out0 = W1@x+b1 -> output channels [0,68). One CTA per (y,b) row, 288 thr.
// ============================================================================
__global__ __launch_bounds__(288, 2) void k1_kernel(
    const float* __restrict__ feature, const float* __restrict__ extra,
    const float* __restrict__ w_ctx,   const float* __restrict__ b_ctx,
    const float* __restrict__ w1,      const float* __restrict__ b1,
    float* __restrict__ out)
{
    extern __shared__ float sm[];
    float* s_wc = sm;            // 1024   : wcT[k*32+o]
    float* s_w1 = sm + 1024;     // 4608   : w1T[k*72+o], o padded 68->72
    float* s_f  = sm + 5632;     // 6144   : feature row [32][192]
    float* s_x  = sm + 11776;    // 12288  : x row [64][192]
    const int tid = threadIdx.x;
    const int y = blockIdx.x, b = blockIdx.y;
    const int fb = b / 3;        // jnp.repeat(...,3,axis=0): [b0,b0,b0,b1,b1,b1]

    for (int idx = tid; idx < 1024; idx += 288) {
        int o = idx >> 5, k = idx & 31;
        s_wc[k*32 + o] = w_ctx[idx];
    }
    for (int idx = tid; idx < 72*64; idx += 288) {
        int o = idx >> 6, k = idx & 63;
        s_w1[k*72 + o] = (o < 68) ? w1[o*64 + k] : 0.f;
    }
    const float* fbase = feature + (fb*32)*HW + y*192;
    const float* ebase = extra   + (b*32)*HW + y*192;
    for (int idx = tid; idx < 32*192; idx += 288) {
        int c = idx / 192, px = idx - c*192;
        s_f[idx]              = fbase[c*HW + px];
        s_x[(32+c)*192 + px]  = ebase[c*HW + px];
    }
    __syncthreads();

    // ctx GEMM: 32 out x 192 px, K=32 (256 threads: 2 out x 12 px each)
    if (tid < 256) {
        const int og = tid >> 4, pg = tid & 15;
        const int o0 = og*2, pxb = pg*12;
        unsigned long long acc[2][6];
        {
            unsigned long long p0 = pk2(b_ctx[o0],   b_ctx[o0]);
            unsigned long long p1 = pk2(b_ctx[o0+1], b_ctx[o0+1]);
            #pragma unroll
            for (int j = 0; j < 6; j++) { acc[0][j] = p0; acc[1][j] = p1; }
        }
        #pragma unroll 4
        for (int k = 0; k < 32; k++) {
            float wa = s_wc[k*32 + o0], wb = s_wc[k*32 + o0 + 1];
            unsigned long long wpa = pk2(wa, wa), wpb = pk2(wb, wb);
            #pragma unroll
            for (int j = 0; j < 6; j++) {
                unsigned long long m =
                    *(const unsigned long long*)(s_f + k*192 + pxb + 2*j);
                fma2(acc[0][j], wpa, m);
                fma2(acc[1][j], wpb, m);
            }
        }
        #pragma unroll
        for (int j = 0; j < 6; j++) {
            *(unsigned long long*)(s_x + o0*192     + pxb + 2*j) = acc[0][j];
            *(unsigned long long*)(s_x + (o0+1)*192 + pxb + 2*j) = acc[1][j];
        }
    }
    __syncthreads();

    // write x row to global
    {
        float* gx = g_x + (b*64)*HW + y*192;
        for (int idx = tid; idx < 64*96; idx += 288) {
            int c = idx / 96, pp = (idx - c*96)*2;
            *(unsigned long long*)(gx + c*HW + pp) =
                *(const unsigned long long*)(s_x + c*192 + pp);
        }
    }

    // out0 GEMM: 72(pad) out x 192 px, K=64 (288 threads: 4 out x 12 px each)
    {
        const int og = tid >> 4, pg = tid & 15;   // og 0..17
        const int o0 = og*4, pxb = pg*12;
        unsigned long long acc[4][6];
        #pragma unroll
        for (int i = 0; i < 4; i++) {
            int o = o0 + i;
            float bb = (o < 68) ? b1[o] : 0.f;
            unsigned long long p = pk2(bb, bb);
            #pragma unroll
            for (int j = 0; j < 6; j++) acc[i][j] = p;
        }
        #pragma unroll 2
        for (int k = 0; k < 64; k++) {
            float4 w4 = *(const float4*)(s_w1 + k*72 + o0);
            unsigned long long w0 = pk2(w4.x, w4.x), wA = pk2(w4.y, w4.y);
            unsigned long long w2 = pk2(w4.z, w4.z), w3 = pk2(w4.w, w4.w);
            #pragma unroll
            for (int j = 0; j < 6; j++) {
                unsigned long long m =
                    *(const unsigned long long*)(s_x + k*192 + pxb + 2*j);
                fma2(acc[0][j], w0, m);
                fma2(acc[1][j], wA, m);
                fma2(acc[2][j], w2, m);
                fma2(acc[3][j], w3, m);
            }
        }
        #pragma unroll
        for (int i = 0; i < 4; i++) {
            int o = o0 + i;
            if (o < 68) {
                float* op = out + (b*260 + o)*HW + y*192 + pxb;
                #pragma unroll
                for (int j = 0; j < 6; j++)
                    *(unsigned long long*)(op + 2*j) = acc[i][j];
            }
        }
    }
}

// ============================================================================
// K2: per-row prefix sums of x and x*x into S1,S2 rows [y+1], with left pad.
// ============================================================================
__global__ void k2_kernel()
{
    const int warp = threadIdx.x >> 5, lane = threadIdx.x & 31;
    const int row  = blockIdx.x * 8 + warp;        // < 6*64*192 = 73728
    const int img  = row / 192, y = row - img*192;
    const float* xr = g_x + row*192;

    float s1p[6], s2p[6];
    float a1 = 0.f, a2 = 0.f;
    #pragma unroll
    for (int j = 0; j < 6; j++) {
        float v = xr[lane*6 + j];
        a1 += v;      s1p[j] = a1;
        a2 += v * v;  s2p[j] = a2;
    }
    float t1 = a1, t2 = a2;
    #pragma unroll
    for (int off = 1; off < 32; off <<= 1) {
        float n1 = __shfl_up_sync(0xffffffffu, t1, off);
        float n2 = __shfl_up_sync(0xffffffffu, t2, off);
        if (lane >= off) { t1 += n1; t2 += n2; }
    }
    float e1 = __shfl_up_sync(0xffffffffu, t1, 1);
    float e2 = __shfl_up_sync(0xffffffffu, t2, 1);
    if (lane == 0) { e1 = 0.f; e2 = 0.f; }

    float* S1r = g_S1 + img*SIMG + (y+1)*193;
    float* S2r = g_S2 + img*SIMG + (y+1)*193;
    if (lane == 0) { S1r[0] = 0.f; S2r[0] = 0.f; }
    #pragma unroll
    for (int j = 0; j < 6; j++) {
        S1r[1 + lane*6 + j] = e1 + s1p[j];
        S2r[1 + lane*6 + j] = e2 + s2p[j];
    }
    if (y == 0) {  // zero pad row 0
        float* Z1 = g_S1 + img*SIMG;
        float* Z2 = g_S2 + img*SIMG;
        for (int j = lane; j < 193; j += 32) { Z1[j] = 0.f; Z2[j] = 0.f; }
    }
}

// ============================================================================
// K3: in-place column accumulation -> full 2D integral images.
// ============================================================================
__global__ void k3_kernel()
{
    const int img = blockIdx.x;
    float* S = ((blockIdx.y == 0) ? g_S1 : g_S2) + img*SIMG;
    const int t = threadIdx.x;
    if (t >= 193) return;
    float s = 0.f;
    float v[8];
    #pragma unroll
    for (int j = 0; j < 8; j++) v[j] = S[(1 + j)*193 + t];
    for (int r0 = 1; r0 <= 192; r0 += 8) {
        float w[8];
        if (r0 + 8 <= 192) {
            #pragma unroll
            for (int j = 0; j < 8; j++) w[j] = S[(r0 + 8 + j)*193 + t];
        }
        #pragma unroll
        for (int j = 0; j < 8; j++) { s += v[j]; S[(r0 + j)*193 + t] = s; }
        #pragma unroll
        for (int j = 0; j < 8; j++) v[j] = w[j];
    }
}

// ============================================================================
// K4 v11 = v10 (best measured) + anti-phase chunk staggering:
//   odd-parity CTAs process K-chunk 1 before chunk 0, so when an even and an
//   odd CTA share an SM, one is in FMA-heavy phase B while the other runs its
//   dependent-LDG phase A — breaking the phase-lock that left phase-A latency
//   exposed. Per-CTA chunk order is fixed by blockIdx (deterministic).
//   All tiling identical to v10: 8-warp CTA (balanced 2/SMSP), warp=32o x 48px,
//   lane=8o x 6px (3 px-pairs @16B stride), 14 wf : 24 fma2 per warp-k.
// ============================================================================
__global__ __launch_bounds__(256, 2) void k4_kernel(
    const float* __restrict__ ws0, const float* __restrict__ bs0,
    const float* __restrict__ ws1, const float* __restrict__ bs1,
    const float* __restrict__ ws2, const float* __restrict__ bs2,
    float* __restrict__ out)
{
    extern __shared__ float sm[];
    float* s_w = sm;            // 8192  : wT[k*64+o]
    float* s_m = sm + 8192;     // 12288 : [64 k][192 px] chunk of mean/var
    float* s_d = sm + 20480;    // 3328  : per-warp D1/D2 (208 each)
    const int tid = threadIdx.x, warp = tid >> 5, lane = tid & 31;
    const int so = lane >> 3, sp = lane & 7;     // out-sub, px-sub
    const int ogx = warp >> 2, pg = warp & 3;    // out-half, px-quarter (48px)
    const int y = blockIdx.x;
    const int z = blockIdx.y;
    const int scale = z / 6, b = z - scale*6;
    const int half = (scale == 0) ? 2 : (scale == 1) ? 4 : 8;
    const float* ws = (scale == 0) ? ws0 : (scale == 1) ? ws1 : ws2;
    const float* bs = (scale == 0) ? bs0 : (scale == 1) ? bs1 : bs2;
    const int par = (int)(blockIdx.x & 1);       // chunk-order stagger parity

    // load + transpose weights: s_w[k*64+o] = ws[o*128+k]
    for (int idx = tid; idx < 8192; idx += 256) {
        int o = idx >> 7, k = idx & 127;
        s_w[k*64 + o] = ws[idx];
    }

    const int y0 = max(y - half, 0);
    const int y1 = min(y + 1 + half, 192);
    const float hh = (float)(y1 - y0);
    const int offA = y0*193, offB = y1*193;

    // phase-A per-lane inverse areas (px = lane + 32*q)
    float inva6[6];
    #pragma unroll
    for (int q = 0; q < 6; q++) {
        int px = lane + 32*q;
        int x0 = max(px - half, 0), x1 = min(px + 1 + half, 192);
        inva6[q] = 1.0f / (hh * (float)(x1 - x0));
    }

    float* D1 = s_d + warp * 416;
    float* D2 = D1 + 208;

    // accumulators: 8 outs x 3 px-pairs, bias-initialized
    const int obase = ogx*32 + so*8;
    unsigned long long acc[8][3];
    #pragma unroll
    for (int i = 0; i < 8; i++) {
        float bb = bs[obase + i];
        unsigned long long p = pk2(bb, bb);
        acc[i][0] = p; acc[i][1] = p; acc[i][2] = p;
    }

    #pragma unroll
    for (int cc = 0; cc < 2; cc++) {
        const int chunk = cc ^ par;            // stagger: odd CTAs do 1 then 0
        const int chb = chunk * 32;
        // ------- Phase A: channels chb..chb+31, 4 per warp -------
        #pragma unroll
        for (int i = 0; i < 4; i++) {
            const int c = warp + 8*i;              // local channel in [0,32)
            const float* p1 = g_S1 + (b*64 + chb + c)*SIMG;
            const float* p2 = g_S2 + (b*64 + chb + c)*SIMG;
            #pragma unroll
            for (int jj = 0; jj < 7; jj++) {
                int j = lane + 32*jj;
                if (j < 193) {
                    D1[j] = p1[offB + j] - p1[offA + j];
                    D2[j] = p2[offB + j] - p2[offA + j];
                }
            }
            __syncwarp();
            #pragma unroll
            for (int q = 0; q < 6; q++) {
                int px = lane + 32*q;
                int i0 = max(px - half, 0);
                int i1 = min(px + 1 + half, 192);
                float s1 = D1[i1] - D1[i0];
                float s2 = D2[i1] - D2[i0];
                float m = s1 * inva6[q];
                float v = s2 * inva6[q] - m*m;
                s_m[c*192 + px]        = m;
                s_m[(32 + c)*192 + px] = v;
            }
            __syncwarp();
        }
        __syncthreads();

        // ------- Phase B: 64-k GEMM slice -------
        #pragma unroll
        for (int hsel = 0; hsel < 2; hsel++) {
            // weight k rows: hsel=0 -> mean ks (chb..), hsel=1 -> var ks
            const float* wp = s_w + (hsel*64 + chb)*64 + obase;
            const float* mp = s_m + (hsel*32)*192 + pg*48 + sp*2;
            #pragma unroll 4
            for (int kk = 0; kk < 32; kk++) {
                float4 wa = *(const float4*)(wp);
                float4 wb = *(const float4*)(wp + 4);
                unsigned long long m0 = *(const unsigned long long*)(mp);
                unsigned long long m1 = *(const unsigned long long*)(mp + 16);
                unsigned long long m2 = *(const unsigned long long*)(mp + 32);
                unsigned long long w0 = pk2(wa.x, wa.x), w1 = pk2(wa.y, wa.y);
                unsigned long long w2 = pk2(wa.z, wa.z), w3 = pk2(wa.w, wa.w);
                unsigned long long w4 = pk2(wb.x, wb.x), w5 = pk2(wb.y, wb.y);
                unsigned long long w6 = pk2(wb.z, wb.z), w7 = pk2(wb.w, wb.w);
                fma2(acc[0][0], w0, m0); fma2(acc[0][1], w0, m1); fma2(acc[0][2], w0, m2);
                fma2(acc[1][0], w1, m0); fma2(acc[1][1], w1, m1); fma2(acc[1][2], w1, m2);
                fma2(acc[2][0], w2, m0); fma2(acc[2][1], w2, m1); fma2(acc[2][2], w2, m2);
                fma2(acc[3][0], w3, m0); fma2(acc[3][1], w3, m1); fma2(acc[3][2], w3, m2);
                fma2(acc[4][0], w4, m0); fma2(acc[4][1], w4, m1); fma2(acc[4][2], w4, m2);
                fma2(acc[5][0], w5, m0); fma2(acc[5][1], w5, m1); fma2(acc[5][2], w5, m2);
                fma2(acc[6][0], w6, m0); fma2(acc[6][1], w6, m1); fma2(acc[6][2], w6, m2);
                fma2(acc[7][0], w7, m0); fma2(acc[7][1], w7, m1); fma2(acc[7][2], w7, m2);
                wp += 64; mp += 192;
            }
        }
        if (cc == 0) __syncthreads();   // protect s_m before next phase A
    }

    // store: 3 px-pairs per out at +0,+16,+32 floats
    float* ob = out + (b*260 + 68 + scale*64 + obase)*HW + y*192 + pg*48 + sp*2;
    #pragma unroll
    for (int i = 0; i < 8; i++) {
        float* op = ob + i*HW;
        *(unsigned long long*)(op)      = acc[i][0];
        *(unsigned long long*)(op + 16) = acc[i][1];
        *(unsigned long long*)(op + 32) = acc[i][2];
    }
}

// ============================================================================
extern "C" void kernel_launch(void* const* d_in, const int* in_sizes, int n_in,
                              void* d_out, int out_size)
{
    const float* feature = (const float*)d_in[0];
    const float* extra   = (const float*)d_in[1];
    const float* w_ctx   = (const float*)d_in[2];
    const float* b_ctx   = (const float*)d_in[3];
    const float* w1      = (const float*)d_in[4];
    const float* b1      = (const float*)d_in[5];
    const float* ws0     = (const float*)d_in[6];
    const float* bs0     = (const float*)d_in[7];
    const float* ws1     = (const float*)d_in[8];
    const float* bs1     = (const float*)d_in[9];
    const float* ws2     = (const float*)d_in[10];
    const float* bs2     = (const float*)d_in[11];
    float* out = (float*)d_out;

    cudaFuncSetAttribute(k1_kernel, cudaFuncAttributeMaxDynamicSharedMemorySize, 96256);
    cudaFuncSetAttribute(k4_kernel, cudaFuncAttributeMaxDynamicSharedMemorySize, 95744);

    k1_kernel<<<dim3(192, 6), 288, 96256>>>(feature, extra, w_ctx, b_ctx, w1, b1, out);
    k2_kernel<<<9216, 256>>>();
    k3_kernel<<<dim3(384, 2), 224>>>();
    k4_kernel<<<dim3(192, 18), 256, 95744>>>(ws0, bs0, ws1, bs1, ws2, bs2, out);
}